// round 3
// baseline (speedup 1.0000x reference)
#include <cuda_runtime.h>
#include <cuda_bf16.h>

// Problem: GraphSequenceOrderer_53257594470659
// B=32, K=1024, D=256. Output (f32, concatenated):
//   [0, B*K*D)           ordered_slots
//   [B*K*D, B*K*D+B*K)   order (as float)
//   [.. + B*K)           reverse_order (as float)

#define B 32
#define K 1024
#define D 256
#define NBUCKET 256   // 16x16 grid -> hilbert index in [0,256)
#define NWARP 32      // 1024 threads / 32

// int copy of order for the gather kernel (scratch; no allocations allowed)
__device__ int g_order[B * K];

__device__ __forceinline__ int hilbert_index(int x, int y) {
    int d = 0;
#pragma unroll
    for (int s = 8; s > 0; s >>= 1) {
        int rx = (x & s) ? 1 : 0;
        int ry = (y & s) ? 1 : 0;
        d += s * s * ((3 * rx) ^ ry);
        if (ry == 0) {
            if (rx == 1) {
                int t = x;
                x = s - 1 - y;
                y = s - 1 - t;
            } else {
                int t = x; x = y; y = t;
            }
        }
    }
    return d;
}

// One CTA per batch. 1024 threads, one key each.
// Stable counting sort over 256 hilbert buckets.
__global__ __launch_bounds__(1024, 1)
void sort_kernel(const float* __restrict__ centroids,
                 float* __restrict__ out_order_f,
                 float* __restrict__ out_rev_f) {
    const int b = blockIdx.x;
    const int i = threadIdx.x;
    const int lane = i & 31;
    const int warp = i >> 5;

    __shared__ int hist[NBUCKET * NWARP];  // 32 KB, bucket-major [bucket][warp]
    __shared__ int warp_sums[NWARP];

    // --- hilbert key ---
    const float2 c = ((const float2*)centroids)[b * K + i];
    float cxf = fminf(fmaxf(c.x * 15.0f, 0.0f), 15.0f);
    float cyf = fminf(fmaxf(c.y * 15.0f, 0.0f), 15.0f);
    int h = hilbert_index((int)cxf, (int)cyf);

    // --- zero histogram ---
#pragma unroll
    for (int j = 0; j < (NBUCKET * NWARP) / 1024; j++)
        hist[i + j * 1024] = 0;
    __syncthreads();

    // --- per-warp counts + stable intra-warp rank via match ---
    unsigned mask = __match_any_sync(0xffffffffu, h);
    int rank = __popc(mask & ((1u << lane) - 1u));   // # earlier lanes, same bucket
    int leader = __ffs(mask) - 1;
    if (lane == leader)
        hist[h * NWARP + warp] = __popc(mask);
    __syncthreads();

    // --- exclusive scan of 8192 entries (bucket-major => stable order) ---
    int base = i * 8;
    int local[8];
    int lsum = 0;
#pragma unroll
    for (int j = 0; j < 8; j++) { local[j] = hist[base + j]; lsum += local[j]; }

    int v = lsum;
#pragma unroll
    for (int o = 1; o < 32; o <<= 1) {
        int n = __shfl_up_sync(0xffffffffu, v, o);
        if (lane >= o) v += n;
    }
    if (lane == 31) warp_sums[warp] = v;
    __syncthreads();
    if (warp == 0) {
        int w = warp_sums[lane];
        int incl = w;
#pragma unroll
        for (int o = 1; o < 32; o <<= 1) {
            int n = __shfl_up_sync(0xffffffffu, incl, o);
            if (lane >= o) incl += n;
        }
        warp_sums[lane] = incl - w;  // exclusive
    }
    __syncthreads();
    int excl = (v - lsum) + warp_sums[warp];

    int run = excl;
#pragma unroll
    for (int j = 0; j < 8; j++) {
        hist[base + j] = run;
        run += local[j];
    }
    __syncthreads();

    // --- scatter ---
    int pos = hist[h * NWARP + warp] + rank;     // stable output position
    g_order[b * K + pos] = i;
    __stcs(&out_order_f[b * K + pos], (float)i);
    __stcs(&out_rev_f[b * K + i], (float)pos);
}

// Permutation gather: ONE WARP PER HALF-ROW (shortest dependent chain,
// maximum independent chains). 64K warps total.
// 256 threads/block = 8 warps = 4 rows/block; grid = B*K*2/8 = 8192 blocks.
__global__ __launch_bounds__(256)
void gather_kernel(const float4* __restrict__ slots, float4* __restrict__ out) {
    const int gwid = blockIdx.x * 8 + (threadIdx.x >> 5);  // global warp id
    const int lane = threadIdx.x & 31;
    const int row  = gwid >> 1;          // [0, B*K)
    const int half = (gwid & 1) << 5;    // 0 or 32 (float4 offset within row)
    const int bofs = (row >> 10) << 10;  // batch base row (b*K)

    const int src = __ldg(&g_order[row]);   // warp-broadcast load

    const float4 v = __ldg(slots + ((size_t)(bofs + src) << 6) + half + lane);
    __stcs(out + ((size_t)row << 6) + half + lane, v);
}

extern "C" void kernel_launch(void* const* d_in, const int* in_sizes, int n_in,
                              void* d_out, int out_size) {
    const float* slots     = (const float*)d_in[0];
    // d_in[1] = adj: unused by the reference
    const float* centroids = (const float*)d_in[2];

    float* out = (float*)d_out;
    float* out_order = out + (size_t)B * K * D;
    float* out_rev   = out_order + (size_t)B * K;

    sort_kernel<<<B, 1024>>>(centroids, out_order, out_rev);
    gather_kernel<<<(B * K * 2) / 8, 256>>>((const float4*)slots, (float4*)out);
}

// round 4
// speedup vs baseline: 1.0953x; 1.0953x over previous
#include <cuda_runtime.h>
#include <cuda_bf16.h>

// Problem: GraphSequenceOrderer_53257594470659
// B=32, K=1024, D=256. Output (f32, concatenated):
//   [0, B*K*D)           ordered_slots
//   [B*K*D, B*K*D+B*K)   order (as float)
//   [.. + B*K)           reverse_order (as float)

#define B 32
#define K 1024
#define D 256
#define NBUCKET 256   // 16x16 grid -> hilbert index in [0,256)
#define NWARP 32      // 1024 threads / 32

// inverse permutation (position within batch) for the scatter kernel
__device__ int g_rev[B * K];

__device__ __forceinline__ int hilbert_index(int x, int y) {
    int d = 0;
#pragma unroll
    for (int s = 8; s > 0; s >>= 1) {
        int rx = (x & s) ? 1 : 0;
        int ry = (y & s) ? 1 : 0;
        d += s * s * ((3 * rx) ^ ry);
        if (ry == 0) {
            if (rx == 1) {
                int t = x;
                x = s - 1 - y;
                y = s - 1 - t;
            } else {
                int t = x; x = y; y = t;
            }
        }
    }
    return d;
}

// One CTA per batch. 1024 threads, one key each.
// Stable counting sort over 256 hilbert buckets.
__global__ __launch_bounds__(1024, 1)
void sort_kernel(const float* __restrict__ centroids,
                 float* __restrict__ out_order_f,
                 float* __restrict__ out_rev_f) {
    const int b = blockIdx.x;
    const int i = threadIdx.x;
    const int lane = i & 31;
    const int warp = i >> 5;

    __shared__ int hist[NBUCKET * NWARP];  // 32 KB, bucket-major [bucket][warp]
    __shared__ int warp_sums[NWARP];

    // --- hilbert key ---
    const float2 c = ((const float2*)centroids)[b * K + i];
    float cxf = fminf(fmaxf(c.x * 15.0f, 0.0f), 15.0f);
    float cyf = fminf(fmaxf(c.y * 15.0f, 0.0f), 15.0f);
    int h = hilbert_index((int)cxf, (int)cyf);

    // --- zero histogram ---
#pragma unroll
    for (int j = 0; j < (NBUCKET * NWARP) / 1024; j++)
        hist[i + j * 1024] = 0;
    __syncthreads();

    // --- per-warp counts + stable intra-warp rank via match ---
    unsigned mask = __match_any_sync(0xffffffffu, h);
    int rank = __popc(mask & ((1u << lane) - 1u));   // # earlier lanes, same bucket
    int leader = __ffs(mask) - 1;
    if (lane == leader)
        hist[h * NWARP + warp] = __popc(mask);
    __syncthreads();

    // --- exclusive scan of 8192 entries (bucket-major => stable order) ---
    int base = i * 8;
    int local[8];
    int lsum = 0;
#pragma unroll
    for (int j = 0; j < 8; j++) { local[j] = hist[base + j]; lsum += local[j]; }

    int v = lsum;
#pragma unroll
    for (int o = 1; o < 32; o <<= 1) {
        int n = __shfl_up_sync(0xffffffffu, v, o);
        if (lane >= o) v += n;
    }
    if (lane == 31) warp_sums[warp] = v;
    __syncthreads();
    if (warp == 0) {
        int w = warp_sums[lane];
        int incl = w;
#pragma unroll
        for (int o = 1; o < 32; o <<= 1) {
            int n = __shfl_up_sync(0xffffffffu, incl, o);
            if (lane >= o) incl += n;
        }
        warp_sums[lane] = incl - w;  // exclusive
    }
    __syncthreads();
    int excl = (v - lsum) + warp_sums[warp];

    int run = excl;
#pragma unroll
    for (int j = 0; j < 8; j++) {
        hist[base + j] = run;
        run += local[j];
    }
    __syncthreads();

    // --- scatter ---
    int pos = hist[h * NWARP + warp] + rank;     // stable output position
    g_rev[b * K + i] = pos;                      // inverse permutation
    out_order_f[b * K + pos] = (float)i;
    out_rev_f[b * K + i]   = (float)pos;
}

// Permutation SCATTER: out[rev[i]] = slots[i].
// Reads are fully sequential (independent of the index load); the random
// access moves to fire-and-forget stores. One warp per row; 8 warps/block;
// grid = B*K/8 = 4096 blocks.
__global__ __launch_bounds__(256)
void scatter_kernel(const float4* __restrict__ slots, float4* __restrict__ out) {
    const int row  = blockIdx.x * 8 + (threadIdx.x >> 5);  // [0, B*K)
    const int lane = threadIdx.x & 31;
    const int bofs = (row >> 10) << 10;                    // batch base row (b*K)

    // both loads issue immediately; no dependency between them
    const int dst = g_rev[row];                            // warp-broadcast
    const float4* s = slots + ((size_t)row << 6);          // sequential read
    const float4 v0 = s[lane];
    const float4 v1 = s[lane + 32];

    float4* o = out + ((size_t)(bofs + dst) << 6);
    o[lane]      = v0;
    o[lane + 32] = v1;
}

extern "C" void kernel_launch(void* const* d_in, const int* in_sizes, int n_in,
                              void* d_out, int out_size) {
    const float* slots     = (const float*)d_in[0];
    // d_in[1] = adj: unused by the reference
    const float* centroids = (const float*)d_in[2];

    float* out = (float*)d_out;
    float* out_order = out + (size_t)B * K * D;
    float* out_rev   = out_order + (size_t)B * K;

    sort_kernel<<<B, 1024>>>(centroids, out_order, out_rev);
    scatter_kernel<<<(B * K) / 8, 256>>>((const float4*)slots, (float4*)out);
}

// round 5
// speedup vs baseline: 1.1098x; 1.0133x over previous
#include <cuda_runtime.h>
#include <cuda_bf16.h>

// Problem: GraphSequenceOrderer_53257594470659
// B=32, K=1024, D=256. Output (f32, concatenated):
//   [0, B*K*D)           ordered_slots
//   [B*K*D, B*K*D+B*K)   order (as float)
//   [.. + B*K)           reverse_order (as float)

#define B 32
#define K 1024
#define D 256
#define NBUCKET 256   // 16x16 grid -> hilbert index in [0,256)
#define NWARP 32      // 1024 threads / 32

// inverse permutation (position within batch) for the scatter kernel
__device__ int g_rev[B * K];

__device__ __forceinline__ int hilbert_index(int x, int y) {
    int d = 0;
#pragma unroll
    for (int s = 8; s > 0; s >>= 1) {
        int rx = (x & s) ? 1 : 0;
        int ry = (y & s) ? 1 : 0;
        d += s * s * ((3 * rx) ^ ry);
        if (ry == 0) {
            if (rx == 1) {
                int t = x;
                x = s - 1 - y;
                y = s - 1 - t;
            } else {
                int t = x; x = y; y = t;
            }
        }
    }
    return d;
}

// One CTA per batch. 1024 threads, one key each.
// Stable counting sort over 256 hilbert buckets.
__global__ __launch_bounds__(1024, 1)
void sort_kernel(const float* __restrict__ centroids,
                 float* __restrict__ out_order_f,
                 float* __restrict__ out_rev_f) {
    const int b = blockIdx.x;
    const int i = threadIdx.x;
    const int lane = i & 31;
    const int warp = i >> 5;

    __shared__ int hist[NBUCKET * NWARP];  // 32 KB, bucket-major [bucket][warp]
    __shared__ int warp_sums[NWARP];

    // --- hilbert key ---
    const float2 c = ((const float2*)centroids)[b * K + i];
    float cxf = fminf(fmaxf(c.x * 15.0f, 0.0f), 15.0f);
    float cyf = fminf(fmaxf(c.y * 15.0f, 0.0f), 15.0f);
    int h = hilbert_index((int)cxf, (int)cyf);

    // --- zero histogram ---
#pragma unroll
    for (int j = 0; j < (NBUCKET * NWARP) / 1024; j++)
        hist[i + j * 1024] = 0;
    __syncthreads();

    // --- per-warp counts + stable intra-warp rank via match ---
    unsigned mask = __match_any_sync(0xffffffffu, h);
    int rank = __popc(mask & ((1u << lane) - 1u));   // # earlier lanes, same bucket
    int leader = __ffs(mask) - 1;
    if (lane == leader)
        hist[h * NWARP + warp] = __popc(mask);
    __syncthreads();

    // --- exclusive scan of 8192 entries (bucket-major => stable order) ---
    int base = i * 8;
    int local[8];
    int lsum = 0;
#pragma unroll
    for (int j = 0; j < 8; j++) { local[j] = hist[base + j]; lsum += local[j]; }

    int v = lsum;
#pragma unroll
    for (int o = 1; o < 32; o <<= 1) {
        int n = __shfl_up_sync(0xffffffffu, v, o);
        if (lane >= o) v += n;
    }
    if (lane == 31) warp_sums[warp] = v;
    __syncthreads();
    if (warp == 0) {
        int w = warp_sums[lane];
        int incl = w;
#pragma unroll
        for (int o = 1; o < 32; o <<= 1) {
            int n = __shfl_up_sync(0xffffffffu, incl, o);
            if (lane >= o) incl += n;
        }
        warp_sums[lane] = incl - w;  // exclusive
    }
    __syncthreads();
    int excl = (v - lsum) + warp_sums[warp];

    int run = excl;
#pragma unroll
    for (int j = 0; j < 8; j++) {
        hist[base + j] = run;
        run += local[j];
    }
    __syncthreads();

    // --- scatter ---
    int pos = hist[h * NWARP + warp] + rank;     // stable output position
    g_rev[b * K + i] = pos;                      // inverse permutation
    out_order_f[b * K + pos] = (float)i;
    out_rev_f[b * K + i]   = (float)pos;
}

// Permutation SCATTER, 2 rows per warp: out[rev[i]] = slots[i].
// All 6 loads per thread-slot (2x g_rev broadcast + 4x sequential LDG.128)
// are mutually independent and front-batched -> ~23KB in flight per SM,
// matching the latency-bandwidth product for 8 TB/s.
// 256 threads/block = 8 warps = 16 rows/block; grid = B*K/16 = 2048.
__global__ __launch_bounds__(256)
void scatter_kernel(const float4* __restrict__ slots, float4* __restrict__ out) {
    const int warp = threadIdx.x >> 5;
    const int lane = threadIdx.x & 31;
    const int row0 = (blockIdx.x * 8 + warp) * 2;          // 2 consecutive rows
    const int bofs = (row0 >> 10) << 10;                   // batch base row (b*K)

    // independent index loads (warp-broadcast)
    const int dst0 = g_rev[row0];
    const int dst1 = g_rev[row0 + 1];

    // 4 independent sequential 16B loads (2KB contiguous per warp)
    const float4* s = slots + ((size_t)row0 << 6);
    const float4 v0 = s[lane];
    const float4 v1 = s[lane + 32];
    const float4 v2 = s[lane + 64];
    const float4 v3 = s[lane + 96];

    float4* o0 = out + ((size_t)(bofs + dst0) << 6);
    float4* o1 = out + ((size_t)(bofs + dst1) << 6);
    o0[lane]      = v0;
    o0[lane + 32] = v1;
    o1[lane]      = v2;
    o1[lane + 32] = v3;
}

extern "C" void kernel_launch(void* const* d_in, const int* in_sizes, int n_in,
                              void* d_out, int out_size) {
    const float* slots     = (const float*)d_in[0];
    // d_in[1] = adj: unused by the reference
    const float* centroids = (const float*)d_in[2];

    float* out = (float*)d_out;
    float* out_order = out + (size_t)B * K * D;
    float* out_rev   = out_order + (size_t)B * K;

    sort_kernel<<<B, 1024>>>(centroids, out_order, out_rev);
    scatter_kernel<<<(B * K) / 16, 256>>>((const float4*)slots, (float4*)out);
}